// round 13
// baseline (speedup 1.0000x reference)
#include <cuda_runtime.h>
#include <cuda_fp16.h>
#include <cstdint>

// ---------------- problem constants ----------------
#define N_NODES 50000
#define N_PAD   50048            // 391 * 128
#define R_REL   16
#define B_BASES 8
#define DIM     128
#define E_EDGES 625000
#define NKEYS   (N_NODES * R_REL)
#define NBLK    ((NKEYS + 1023) / 1024)   // 782
#define KDIM    1152             // (B+1)*D : 8 bases + selfw
#define KC      32               // K elements per pipeline stage
#define KCH     (KDIM / KC)      // 36
#define NTILES  (N_PAD / 128)    // 391

// smem tile geometry: 128 rows x KC fp16, padded to 40 elems (80 B) per row
#define TPAD    40
#define ROWB    (TPAD * 2)                // 80 bytes per row
#define TILE_B  (128 * ROWB)              // 10240 bytes
#define SA      0
#define SW      TILE_B                    // 10240
#define STAGE_B (2 * TILE_B)              // A, W = 20480
#define NSTAGE  3                         // stages end at 61440
#define SM_MEAN  67584                    // after Cs (128*132*4 = 67584), overlays stages
#define SM_RS    (SM_MEAN + 512)
#define SM_BIAS  68608
#define SM_G     (SM_BIAS + 512)
#define SM_B2    (SM_G + 512)
#define SM_TOTAL (SM_B2 + 512)            // 70144

// packed edge word: col[0:17) | rel[17:21) | seg_len[21:32)
#define PK_COL(v)  ((v) & 0x1FFFFu)
#define PK_REL(v)  (((v) >> 17) & 0xFu)
#define PK_LEN(v)  ((v) >> 21)

// ---------------- scratch (device globals) ----------------
__device__ int g_hist[NKEYS];
__device__ int g_start[NKEYS + 1];
__device__ int g_cursor[NKEYS];
__device__ int g_bsums[1024];
__device__ uint32_t g_sedge[E_EDGES];           // packed sorted edges
__device__ __half g_Af[(size_t)N_PAD * KDIM];   // [N_pad, 1152] fp16
__device__ float g_x1[(size_t)N_PAD * DIM];     // layer-1 output
__device__ __half g_Wf[2][DIM * KDIM];          // Wt[n][k] fp16, per layer

// ---------------- helpers ----------------
__device__ __forceinline__ uint32_t smem_u32(const void* p) {
    uint32_t a;
    asm("{ .reg .u64 t; cvta.to.shared.u64 t, %1; cvt.u32.u64 %0, t; }" : "=r"(a) : "l"(p));
    return a;
}
__device__ __forceinline__ void cpa16(uint32_t dst, const void* src) {
    asm volatile("cp.async.cg.shared.global [%0], [%1], 16;" :: "r"(dst), "l"(src) : "memory");
}
__device__ __forceinline__ uint32_t lds32(uint32_t a) {
    uint32_t v;
    asm volatile("ld.shared.b32 %0, [%1];" : "=r"(v) : "r"(a));
    return v;
}
__device__ __forceinline__ void mma16816(float* c, uint32_t a0, uint32_t a1, uint32_t a2,
                                         uint32_t a3, uint32_t b0, uint32_t b1) {
    asm volatile(
        "mma.sync.aligned.m16n8k16.row.col.f32.f16.f16.f32 "
        "{%0,%1,%2,%3}, {%4,%5,%6,%7}, {%8,%9}, {%0,%1,%2,%3};"
        : "+f"(c[0]), "+f"(c[1]), "+f"(c[2]), "+f"(c[3])
        : "r"(a0), "r"(a1), "r"(a2), "r"(a3), "r"(b0), "r"(b1));
}
__device__ __forceinline__ uint2 pack4h(float4 f) {
    __half2 h0 = __floats2half2_rn(f.x, f.y);
    __half2 h1 = __floats2half2_rn(f.z, f.w);
    uint2 r;
    r.x = *reinterpret_cast<uint32_t*>(&h0);
    r.y = *reinterpret_cast<uint32_t*>(&h1);
    return r;
}

// ---------------- sort / bookkeeping kernels ----------------
__global__ void k_zero() {
    int i = blockIdx.x * blockDim.x + threadIdx.x;
    if (i < NKEYS) g_hist[i] = 0;
}
__global__ void k_hist(const int* __restrict__ row, const int* __restrict__ et) {
    int e = blockIdx.x * blockDim.x + threadIdx.x;
    if (e < E_EDGES) atomicAdd(&g_hist[row[e] * R_REL + et[e]], 1);
}
__global__ void k_scan1() {
    __shared__ int sh[1024];
    int tid = threadIdx.x;
    int i = blockIdx.x * 1024 + tid;
    int v = (i < NKEYS) ? g_hist[i] : 0;
    sh[tid] = v;
    __syncthreads();
    for (int off = 1; off < 1024; off <<= 1) {
        int t = (tid >= off) ? sh[tid - off] : 0;
        __syncthreads();
        sh[tid] += t;
        __syncthreads();
    }
    if (i < NKEYS) g_start[i] = sh[tid] - v;
    if (tid == 1023) g_bsums[blockIdx.x] = sh[1023];
}
__global__ void k_scan2() {
    __shared__ int sh[1024];
    int tid = threadIdx.x;
    int v = (tid < NBLK) ? g_bsums[tid] : 0;
    sh[tid] = v;
    __syncthreads();
    for (int off = 1; off < 1024; off <<= 1) {
        int t = (tid >= off) ? sh[tid - off] : 0;
        __syncthreads();
        sh[tid] += t;
        __syncthreads();
    }
    if (tid < NBLK) g_bsums[tid] = sh[tid] - v;
}
__global__ void k_scan3() {
    int i = blockIdx.x * 1024 + threadIdx.x;
    if (i < NKEYS) {
        int s = g_start[i] + g_bsums[blockIdx.x];
        g_start[i] = s;
        g_cursor[i] = s;
    }
    if (i == 0) g_start[NKEYS] = E_EDGES;
}
__global__ void k_scatter(const int* __restrict__ row, const int* __restrict__ col,
                          const int* __restrict__ et) {
    int e = blockIdx.x * blockDim.x + threadIdx.x;
    if (e < E_EDGES) {
        int r = et[e];
        int key = row[e] * R_REL + r;
        int p = atomicAdd(&g_cursor[key], 1);
        uint32_t len = (uint32_t)(g_start[key + 1] - g_start[key]);
        if (len > 2047u) len = 2047u;   // practically unreachable (Poisson mean 0.78)
        g_sedge[p] = (uint32_t)col[e] | ((uint32_t)r << 17) | (len << 21);
    }
}

// ---------------- weight prep: tiled transpose [1152,128] -> Wt[n][k] fp16 ----------------
__global__ void k_wprep(const float* __restrict__ bases, const float* __restrict__ selfw, int layer) {
    __shared__ float t[32][33];
    int k0 = blockIdx.x * 32, o0 = blockIdx.y * 32;
    int tx = threadIdx.x, ty = threadIdx.y;  // 32 x 8
#pragma unroll
    for (int j = 0; j < 4; j++) {
        int k = k0 + ty + j * 8;
        int o = o0 + tx;
        float v = (k < 1024) ? bases[(size_t)k * DIM + o] : selfw[(size_t)(k - 1024) * DIM + o];
        t[ty + j * 8][tx] = v;
    }
    __syncthreads();
#pragma unroll
    for (int j = 0; j < 4; j++) {
        int o = o0 + ty + j * 8;
        int k = k0 + tx;
        g_Wf[layer][(size_t)o * KDIM + k] = __float2half(t[tx][ty + j * 8]);
    }
}

// ---------------- aggregation: one warp per node, flat edge loop, 8-deep pipeline ----------
__global__ void k_agg(const float* __restrict__ x0, const float* __restrict__ coef, int layer) {
    __shared__ float sc[R_REL * B_BASES];
    int tid = threadIdx.x;
    if (tid < R_REL * B_BASES) sc[tid] = coef[tid];
    __syncthreads();

    const float* x = layer ? g_x1 : x0;
    int n = (blockIdx.x * blockDim.x + tid) >> 5;
    int lane = tid & 31;
    if (n >= N_NODES) return;

    float4 u[B_BASES];
#pragma unroll
    for (int b = 0; b < B_BASES; b++) u[b] = make_float4(0.f, 0.f, 0.f, 0.f);

    const float4* x4 = (const float4*)x;
    int base = n * R_REL;
    int p0 = g_start[base];
    int pE = g_start[base + R_REL];
    int deg = pE - p0;

    if (deg > 0) {
        uint32_t pk[8];
        float4 vv[8];
#pragma unroll
        for (int j = 0; j < 8; j++) {
            if (j < deg) {
                pk[j] = g_sedge[p0 + j];
                vv[j] = x4[(size_t)PK_COL(pk[j]) * 32 + lane];
            }
        }

        int rprev = -1;
        float cw[B_BASES];
#pragma unroll
        for (int b = 0; b < B_BASES; b++) cw[b] = 0.f;

        for (int q0 = 0; q0 < deg; q0 += 8) {
#pragma unroll
            for (int jj = 0; jj < 8; jj++) {
                int q = q0 + jj;
                if (q >= deg) break;
                uint32_t pkc = pk[jj];
                float4 v = vv[jj];
                int qn = q + 8;
                if (qn < deg) {
                    uint32_t pk2 = g_sedge[p0 + qn];
                    pk[jj] = pk2;
                    vv[jj] = x4[(size_t)PK_COL(pk2) * 32 + lane];
                }
                int r = (int)PK_REL(pkc);
                if (r != rprev) {
                    rprev = r;
                    float inv = 1.0f / (float)PK_LEN(pkc);
#pragma unroll
                    for (int b = 0; b < B_BASES; b++) cw[b] = sc[r * B_BASES + b] * inv;
                }
#pragma unroll
                for (int b = 0; b < B_BASES; b++) {
                    u[b].x += cw[b] * v.x;
                    u[b].y += cw[b] * v.y;
                    u[b].z += cw[b] * v.z;
                    u[b].w += cw[b] * v.w;
                }
            }
        }
    }

    size_t arow = (size_t)n * KDIM;
#pragma unroll
    for (int b = 0; b < B_BASES; b++)
        *(uint2*)(g_Af + arow + b * 128 + lane * 4) = pack4h(u[b]);
    *(uint2*)(g_Af + arow + 1024 + lane * 4) = pack4h(x4[(size_t)n * 32 + lane]);
}

// ---------------- fused GEMM (fp16, 3-stage cp.async, scalar LDS) + bias + LN + ReLU -------
__global__ void __launch_bounds__(256, 2) k_gemm(const float* __restrict__ bias,
                                                 const float* __restrict__ lng,
                                                 const float* __restrict__ lnb,
                                                 int layer, float* __restrict__ out_l2) {
    extern __shared__ char smem[];
    uint32_t sb = smem_u32(smem);
    int tid = threadIdx.x;
    int wid = tid >> 5, lane = tid & 31;
    int g = lane >> 2, tig = lane & 3;
    int wm = wid & 1, wn = wid >> 1;   // 2 x 4 warp grid over 128x128
    int n0 = blockIdx.x * 128;

    if (tid < 128) {
        ((float*)(smem + SM_BIAS))[tid] = bias[tid];
        ((float*)(smem + SM_G))[tid] = lng[tid];
        ((float*)(smem + SM_B2))[tid] = lnb[tid];
    }

    const __half* Wf = g_Wf[layer];
    float* out = layer ? out_l2 : g_x1;

    float c[4][4][4];
#pragma unroll
    for (int i = 0; i < 4; i++)
#pragma unroll
        for (int j = 0; j < 4; j++)
#pragma unroll
            for (int q = 0; q < 4; q++) c[i][j][q] = 0.f;

    // cp.async stage issue: 2 tiles x 128 rows x 64B; per thread 4 chunks of 16B
    int crow = tid >> 2;               // 0..63
    int cn = tid & 3;
    int coff = cn * 8;                 // fp16 element offset of 16B chunk
    size_t abase = (size_t)n0 * KDIM;

    auto issue = [&](int kc) {
        uint32_t d = sb + (kc % NSTAGE) * STAGE_B + crow * ROWB + cn * 16;
        size_t go = (size_t)crow * KDIM + kc * KC + coff;
        cpa16(d + SA, g_Af + abase + go);
        cpa16(d + SA + 64 * ROWB, g_Af + abase + go + (size_t)64 * KDIM);
        cpa16(d + SW, Wf + go);
        cpa16(d + SW + 64 * ROWB, Wf + go + (size_t)64 * KDIM);
        asm volatile("cp.async.commit_group;" ::: "memory");
    };

    issue(0);
    issue(1);

    for (int kc = 0; kc < KCH; kc++) {
        if (kc + 1 < KCH) {
            asm volatile("cp.async.wait_group 1;" ::: "memory");
        } else {
            asm volatile("cp.async.wait_group 0;" ::: "memory");
        }
        __syncthreads();
        if (kc + 2 < KCH) issue(kc + 2);

        uint32_t tA = sb + (kc % NSTAGE) * STAGE_B + SA;
        uint32_t tW = sb + (kc % NSTAGE) * STAGE_B + SW;

#pragma unroll
        for (int ks = 0; ks < 2; ks++) {
            int kb = ks * 16;
            uint32_t bh[4][2];
#pragma unroll
            for (int nf = 0; nf < 4; nf++) {
                int n = wn * 32 + nf * 8 + g;
                uint32_t o0 = n * ROWB + (kb + 2 * tig) * 2;
                bh[nf][0] = lds32(tW + o0);
                bh[nf][1] = lds32(tW + o0 + 16);
            }
#pragma unroll
            for (int mf = 0; mf < 4; mf++) {
                int r0 = wm * 64 + mf * 16 + g;
                uint32_t p = r0 * ROWB + (kb + 2 * tig) * 2;
                uint32_t a0 = lds32(tA + p);
                uint32_t a1 = lds32(tA + p + 8 * ROWB);
                uint32_t a2 = lds32(tA + p + 16);
                uint32_t a3 = lds32(tA + p + 8 * ROWB + 16);
#pragma unroll
                for (int nf = 0; nf < 4; nf++)
                    mma16816(c[mf][nf], a0, a1, a2, a3, bh[nf][0], bh[nf][1]);
            }
        }
    }
    __syncthreads();

    // ---- epilogue: C -> smem, LN stats, coalesced store ----
    float* Cs = (float*)smem;  // [128][132]
#pragma unroll
    for (int mf = 0; mf < 4; mf++) {
#pragma unroll
        for (int nf = 0; nf < 4; nf++) {
            int r0 = wm * 64 + mf * 16 + g;
            int cc = wn * 32 + nf * 8 + 2 * tig;
            Cs[r0 * 132 + cc] = c[mf][nf][0];
            Cs[r0 * 132 + cc + 1] = c[mf][nf][1];
            Cs[(r0 + 8) * 132 + cc] = c[mf][nf][2];
            Cs[(r0 + 8) * 132 + cc + 1] = c[mf][nf][3];
        }
    }
    __syncthreads();

    float* smean = (float*)(smem + SM_MEAN);
    float* srs = (float*)(smem + SM_RS);
    const float4* bp = (const float4*)(smem + SM_BIAS);

    if (tid < 128) {
        const float4* rowp = (const float4*)(Cs + tid * 132);
        float mean = 0.f;
#pragma unroll
        for (int i = 0; i < 32; i++) {
            float4 v = rowp[i], bi = bp[i];
            mean += (v.x + bi.x) + (v.y + bi.y) + (v.z + bi.z) + (v.w + bi.w);
        }
        mean *= (1.0f / 128.0f);
        float var = 0.f;
#pragma unroll
        for (int i = 0; i < 32; i++) {
            float4 v = rowp[i], bi = bp[i];
            float d0 = v.x + bi.x - mean, d1 = v.y + bi.y - mean;
            float d2 = v.z + bi.z - mean, d3 = v.w + bi.w - mean;
            var += d0 * d0 + d1 * d1 + d2 * d2 + d3 * d3;
        }
        smean[tid] = mean;
        srs[tid] = rsqrtf(var * (1.0f / 128.0f) + 1e-5f);
    }
    __syncthreads();

    const float4* gp = (const float4*)(smem + SM_G);
    const float4* bbp = (const float4*)(smem + SM_B2);
#pragma unroll
    for (int it = 0; it < 16; it++) {
        int idx = tid + it * 256;      // float4 index over 128x32
        int rrow = idx >> 5, c4 = idx & 31;
        int node = n0 + rrow;
        if (node < N_NODES) {
            float m = smean[rrow], rs = srs[rrow];
            float4 v = ((const float4*)(Cs + rrow * 132))[c4];
            float4 bi = bp[c4], gg = gp[c4], be = bbp[c4];
            float4 w;
            w.x = fmaxf((v.x + bi.x - m) * rs * gg.x + be.x, 0.f);
            w.y = fmaxf((v.y + bi.y - m) * rs * gg.y + be.y, 0.f);
            w.z = fmaxf((v.z + bi.z - m) * rs * gg.z + be.z, 0.f);
            w.w = fmaxf((v.w + bi.w - m) * rs * gg.w + be.w, 0.f);
            ((float4*)(out + (size_t)node * DIM))[c4] = w;
        }
    }
}

// ---------------- launch ----------------
extern "C" void kernel_launch(void* const* d_in, const int* in_sizes, int n_in,
                              void* d_out, int out_size) {
    const int* ei = (const int*)d_in[0];
    const int* row = ei;
    const int* col = ei + E_EDGES;
    const int* et = (const int*)d_in[1];
    const float* emb = (const float*)d_in[2];
    const float* bases1 = (const float*)d_in[3];
    const float* coef1 = (const float*)d_in[4];
    const float* selfw1 = (const float*)d_in[5];
    const float* bias1 = (const float*)d_in[6];
    const float* g1 = (const float*)d_in[7];
    const float* b1 = (const float*)d_in[8];
    const float* bases2 = (const float*)d_in[9];
    const float* coef2 = (const float*)d_in[10];
    const float* selfw2 = (const float*)d_in[11];
    const float* bias2 = (const float*)d_in[12];
    const float* g2 = (const float*)d_in[13];
    const float* b2 = (const float*)d_in[14];
    float* out = (float*)d_out;

    static bool attr_set = false;
    if (!attr_set) {
        cudaFuncSetAttribute(k_gemm, cudaFuncAttributeMaxDynamicSharedMemorySize, SM_TOTAL);
        attr_set = true;
    }

    // edge sort by (row, relation) — shared by both layers
    k_zero<<<(NKEYS + 255) / 256, 256>>>();
    k_hist<<<(E_EDGES + 255) / 256, 256>>>(row, et);
    k_scan1<<<NBLK, 1024>>>();
    k_scan2<<<1, 1024>>>();
    k_scan3<<<NBLK, 1024>>>();
    k_scatter<<<(E_EDGES + 255) / 256, 256>>>(row, col, et);

    // weight prep (tiled transpose, fp16)
    dim3 wgrid(KDIM / 32, DIM / 32);
    dim3 wblk(32, 8);
    k_wprep<<<wgrid, wblk>>>(bases1, selfw1, 0);
    k_wprep<<<wgrid, wblk>>>(bases2, selfw2, 1);

    // layer 1
    k_agg<<<(N_NODES * 32 + 255) / 256, 256>>>(emb, coef1, 0);
    k_gemm<<<NTILES, 256, SM_TOTAL>>>(bias1, g1, b1, 0, out);
    // layer 2
    k_agg<<<(N_NODES * 32 + 255) / 256, 256>>>(emb, coef2, 1);
    k_gemm<<<NTILES, 256, SM_TOTAL>>>(bias2, g2, b2, 1, out);
}

// round 14
// speedup vs baseline: 1.6937x; 1.6937x over previous
#include <cuda_runtime.h>
#include <cuda_fp16.h>
#include <cstdint>

// ---------------- problem constants ----------------
#define N_NODES 50000
#define N_PAD   50048            // 391 * 128
#define R_REL   16
#define B_BASES 8
#define DIM     128
#define E_EDGES 625000
#define NKEYS   (N_NODES * R_REL)
#define NBLK    ((NKEYS + 1023) / 1024)   // 782
#define KDIM    1152             // (B+1)*D : 8 bases + selfw
#define KC      32               // K elements per pipeline stage
#define KCH     (KDIM / KC)      // 36
#define NTILES  (N_PAD / 128)    // 391

// smem tile geometry: 128 rows x KC fp16, padded to 40 elems (80 B) per row
#define TPAD    40
#define ROWB    (TPAD * 2)                // 80 bytes per row
#define TILE_B  (128 * ROWB)              // 10240 bytes
#define SA      0
#define SW      TILE_B                    // 10240
#define STAGE_B (2 * TILE_B)              // A, W = 20480
#define NSTAGE  3                         // stages end at 61440
#define SM_MEAN  67584                    // after Cs (128*132*4 = 67584), overlays stages
#define SM_RS    (SM_MEAN + 512)
#define SM_BIAS  68608
#define SM_G     (SM_BIAS + 512)
#define SM_B2    (SM_G + 512)
#define SM_TOTAL (SM_B2 + 512)            // 70144

// ---------------- scratch (device globals) ----------------
__device__ int g_hist[NKEYS];
__device__ int g_start[NKEYS + 1];
__device__ int g_cursor[NKEYS];
__device__ int g_bsums[1024];
__device__ int g_scol[E_EDGES];
__device__ __half g_Af[(size_t)N_PAD * KDIM];   // [N_pad, 1152] fp16
__device__ __half g_xh[(size_t)N_NODES * DIM];  // emb as fp16
__device__ __half g_x1h[(size_t)N_NODES * DIM]; // layer-1 output as fp16
__device__ __half g_Wf[2][DIM * KDIM];          // Wt[n][k] fp16, per layer

// ---------------- helpers ----------------
__device__ __forceinline__ uint32_t smem_u32(const void* p) {
    uint32_t a;
    asm("{ .reg .u64 t; cvta.to.shared.u64 t, %1; cvt.u32.u64 %0, t; }" : "=r"(a) : "l"(p));
    return a;
}
__device__ __forceinline__ void cpa16(uint32_t dst, const void* src) {
    asm volatile("cp.async.cg.shared.global [%0], [%1], 16;" :: "r"(dst), "l"(src) : "memory");
}
__device__ __forceinline__ uint32_t lds32(uint32_t a) {
    uint32_t v;
    asm volatile("ld.shared.b32 %0, [%1];" : "=r"(v) : "r"(a));
    return v;
}
__device__ __forceinline__ void mma16816(float* c, uint32_t a0, uint32_t a1, uint32_t a2,
                                         uint32_t a3, uint32_t b0, uint32_t b1) {
    asm volatile(
        "mma.sync.aligned.m16n8k16.row.col.f32.f16.f16.f32 "
        "{%0,%1,%2,%3}, {%4,%5,%6,%7}, {%8,%9}, {%0,%1,%2,%3};"
        : "+f"(c[0]), "+f"(c[1]), "+f"(c[2]), "+f"(c[3])
        : "r"(a0), "r"(a1), "r"(a2), "r"(a3), "r"(b0), "r"(b1));
}
__device__ __forceinline__ uint2 pack4h(float4 f) {
    __half2 h0 = __floats2half2_rn(f.x, f.y);
    __half2 h1 = __floats2half2_rn(f.z, f.w);
    uint2 r;
    r.x = *reinterpret_cast<uint32_t*>(&h0);
    r.y = *reinterpret_cast<uint32_t*>(&h1);
    return r;
}
__device__ __forceinline__ float4 unpack4h(uint2 v) {
    float2 f0 = __half22float2(*reinterpret_cast<__half2*>(&v.x));
    float2 f1 = __half22float2(*reinterpret_cast<__half2*>(&v.y));
    return make_float4(f0.x, f0.y, f1.x, f1.y);
}

// ---------------- sort / bookkeeping kernels ----------------
__global__ void k_zero() {
    int i = blockIdx.x * blockDim.x + threadIdx.x;
    if (i < NKEYS) g_hist[i] = 0;
}
__global__ void k_hist(const int* __restrict__ row, const int* __restrict__ et) {
    int e = blockIdx.x * blockDim.x + threadIdx.x;
    if (e < E_EDGES) atomicAdd(&g_hist[row[e] * R_REL + et[e]], 1);
}
__global__ void k_scan1() {
    __shared__ int sh[1024];
    int tid = threadIdx.x;
    int i = blockIdx.x * 1024 + tid;
    int v = (i < NKEYS) ? g_hist[i] : 0;
    sh[tid] = v;
    __syncthreads();
    for (int off = 1; off < 1024; off <<= 1) {
        int t = (tid >= off) ? sh[tid - off] : 0;
        __syncthreads();
        sh[tid] += t;
        __syncthreads();
    }
    if (i < NKEYS) g_start[i] = sh[tid] - v;
    if (tid == 1023) g_bsums[blockIdx.x] = sh[1023];
}
__global__ void k_scan2() {
    __shared__ int sh[1024];
    int tid = threadIdx.x;
    int v = (tid < NBLK) ? g_bsums[tid] : 0;
    sh[tid] = v;
    __syncthreads();
    for (int off = 1; off < 1024; off <<= 1) {
        int t = (tid >= off) ? sh[tid - off] : 0;
        __syncthreads();
        sh[tid] += t;
        __syncthreads();
    }
    if (tid < NBLK) g_bsums[tid] = sh[tid] - v;
}
__global__ void k_scan3() {
    int i = blockIdx.x * 1024 + threadIdx.x;
    if (i < NKEYS) {
        int s = g_start[i] + g_bsums[blockIdx.x];
        g_start[i] = s;
        g_cursor[i] = s;
    }
    if (i == 0) g_start[NKEYS] = E_EDGES;
}
__global__ void k_scatter(const int* __restrict__ row, const int* __restrict__ col,
                          const int* __restrict__ et) {
    int e = blockIdx.x * blockDim.x + threadIdx.x;
    if (e < E_EDGES) {
        int key = row[e] * R_REL + et[e];
        int p = atomicAdd(&g_cursor[key], 1);
        g_scol[p] = col[e];
    }
}

// ---------------- emb -> fp16 ----------------
__global__ void k_cvt(const float* __restrict__ emb) {
    int i = blockIdx.x * blockDim.x + threadIdx.x;   // one float4 each
    if (i < N_NODES * 32) {
        float4 v = ((const float4*)emb)[i];
        ((uint2*)g_xh)[i] = pack4h(v);
    }
}

// ---------------- weight prep: tiled transpose [1152,128] -> Wt[n][k] fp16 ----------------
__global__ void k_wprep(const float* __restrict__ bases, const float* __restrict__ selfw, int layer) {
    __shared__ float t[32][33];
    int k0 = blockIdx.x * 32, o0 = blockIdx.y * 32;
    int tx = threadIdx.x, ty = threadIdx.y;  // 32 x 8
#pragma unroll
    for (int j = 0; j < 4; j++) {
        int k = k0 + ty + j * 8;
        int o = o0 + tx;
        float v = (k < 1024) ? bases[(size_t)k * DIM + o] : selfw[(size_t)(k - 1024) * DIM + o];
        t[ty + j * 8][tx] = v;
    }
    __syncthreads();
#pragma unroll
    for (int j = 0; j < 4; j++) {
        int o = o0 + ty + j * 8;
        int k = k0 + tx;
        g_Wf[layer][(size_t)o * KDIM + k] = __float2half(t[tx][ty + j * 8]);
    }
}

// ---------------- aggregation: R12 structure, fp16 gathers ----------------
__global__ void k_agg(const float* __restrict__ coef, int layer) {
    __shared__ float sc[R_REL * B_BASES];
    int tid = threadIdx.x;
    if (tid < R_REL * B_BASES) sc[tid] = coef[tid];
    __syncthreads();

    const uint2* x2 = layer ? (const uint2*)g_x1h : (const uint2*)g_xh;
    int n = (blockIdx.x * blockDim.x + tid) >> 5;
    int lane = tid & 31;
    if (n >= N_NODES) return;

    float4 u[B_BASES];
#pragma unroll
    for (int b = 0; b < B_BASES; b++) u[b] = make_float4(0.f, 0.f, 0.f, 0.f);

    int base = n * R_REL;
    for (int r = 0; r < R_REL; r++) {
        int s = g_start[base + r];
        int e1 = g_start[base + r + 1];
        if (e1 > s) {
            float4 a0 = make_float4(0.f, 0.f, 0.f, 0.f);
            float4 a1 = make_float4(0.f, 0.f, 0.f, 0.f);
            int e = s;
            // 4-wide: 4 index loads + 4 gathers in flight per iteration
            for (; e + 4 <= e1; e += 4) {
                int c0 = g_scol[e], c1 = g_scol[e + 1];
                int c2 = g_scol[e + 2], c3 = g_scol[e + 3];
                float4 v0 = unpack4h(x2[(size_t)c0 * 32 + lane]);
                float4 v1 = unpack4h(x2[(size_t)c1 * 32 + lane]);
                float4 v2 = unpack4h(x2[(size_t)c2 * 32 + lane]);
                float4 v3 = unpack4h(x2[(size_t)c3 * 32 + lane]);
                a0.x += v0.x + v2.x; a0.y += v0.y + v2.y;
                a0.z += v0.z + v2.z; a0.w += v0.w + v2.w;
                a1.x += v1.x + v3.x; a1.y += v1.y + v3.y;
                a1.z += v1.z + v3.z; a1.w += v1.w + v3.w;
            }
            for (; e < e1; e++) {
                int c = g_scol[e];
                float4 v = unpack4h(x2[(size_t)c * 32 + lane]);
                a0.x += v.x; a0.y += v.y; a0.z += v.z; a0.w += v.w;
            }
            float4 acc;
            acc.x = a0.x + a1.x; acc.y = a0.y + a1.y;
            acc.z = a0.z + a1.z; acc.w = a0.w + a1.w;
            float inv = 1.0f / (float)(e1 - s);
#pragma unroll
            for (int b = 0; b < B_BASES; b++) {
                float cb = sc[r * B_BASES + b] * inv;
                u[b].x += cb * acc.x; u[b].y += cb * acc.y;
                u[b].z += cb * acc.z; u[b].w += cb * acc.w;
            }
        }
    }

    size_t arow = (size_t)n * KDIM;
#pragma unroll
    for (int b = 0; b < B_BASES; b++)
        *(uint2*)(g_Af + arow + b * 128 + lane * 4) = pack4h(u[b]);
    // self columns: x already fp16 — straight copy
    *(uint2*)(g_Af + arow + 1024 + lane * 4) = x2[(size_t)n * 32 + lane];
}

// ---------------- fused GEMM (fp16, 3-stage cp.async, scalar LDS) + bias + LN + ReLU -------
__global__ void __launch_bounds__(256, 2) k_gemm(const float* __restrict__ bias,
                                                 const float* __restrict__ lng,
                                                 const float* __restrict__ lnb,
                                                 int layer, float* __restrict__ out_l2) {
    extern __shared__ char smem[];
    uint32_t sb = smem_u32(smem);
    int tid = threadIdx.x;
    int wid = tid >> 5, lane = tid & 31;
    int g = lane >> 2, tig = lane & 3;
    int wm = wid & 1, wn = wid >> 1;   // 2 x 4 warp grid over 128x128
    int n0 = blockIdx.x * 128;

    if (tid < 128) {
        ((float*)(smem + SM_BIAS))[tid] = bias[tid];
        ((float*)(smem + SM_G))[tid] = lng[tid];
        ((float*)(smem + SM_B2))[tid] = lnb[tid];
    }

    const __half* Wf = g_Wf[layer];

    float c[4][4][4];
#pragma unroll
    for (int i = 0; i < 4; i++)
#pragma unroll
        for (int j = 0; j < 4; j++)
#pragma unroll
            for (int q = 0; q < 4; q++) c[i][j][q] = 0.f;

    // cp.async stage issue: 2 tiles x 128 rows x 64B; per thread 4 chunks of 16B
    int crow = tid >> 2;               // 0..63
    int cn = tid & 3;
    int coff = cn * 8;                 // fp16 element offset of 16B chunk
    size_t abase = (size_t)n0 * KDIM;

    auto issue = [&](int kc) {
        uint32_t d = sb + (kc % NSTAGE) * STAGE_B + crow * ROWB + cn * 16;
        size_t go = (size_t)crow * KDIM + kc * KC + coff;
        cpa16(d + SA, g_Af + abase + go);
        cpa16(d + SA + 64 * ROWB, g_Af + abase + go + (size_t)64 * KDIM);
        cpa16(d + SW, Wf + go);
        cpa16(d + SW + 64 * ROWB, Wf + go + (size_t)64 * KDIM);
        asm volatile("cp.async.commit_group;" ::: "memory");
    };

    issue(0);
    issue(1);

    for (int kc = 0; kc < KCH; kc++) {
        if (kc + 1 < KCH) {
            asm volatile("cp.async.wait_group 1;" ::: "memory");
        } else {
            asm volatile("cp.async.wait_group 0;" ::: "memory");
        }
        __syncthreads();
        if (kc + 2 < KCH) issue(kc + 2);

        uint32_t tA = sb + (kc % NSTAGE) * STAGE_B + SA;
        uint32_t tW = sb + (kc % NSTAGE) * STAGE_B + SW;

#pragma unroll
        for (int ks = 0; ks < 2; ks++) {
            int kb = ks * 16;
            uint32_t bh[4][2];
#pragma unroll
            for (int nf = 0; nf < 4; nf++) {
                int n = wn * 32 + nf * 8 + g;
                uint32_t o0 = n * ROWB + (kb + 2 * tig) * 2;
                bh[nf][0] = lds32(tW + o0);
                bh[nf][1] = lds32(tW + o0 + 16);
            }
#pragma unroll
            for (int mf = 0; mf < 4; mf++) {
                int r0 = wm * 64 + mf * 16 + g;
                uint32_t p = r0 * ROWB + (kb + 2 * tig) * 2;
                uint32_t a0 = lds32(tA + p);
                uint32_t a1 = lds32(tA + p + 8 * ROWB);
                uint32_t a2 = lds32(tA + p + 16);
                uint32_t a3 = lds32(tA + p + 8 * ROWB + 16);
#pragma unroll
                for (int nf = 0; nf < 4; nf++)
                    mma16816(c[mf][nf], a0, a1, a2, a3, bh[nf][0], bh[nf][1]);
            }
        }
    }
    __syncthreads();

    // ---- epilogue: C -> smem, LN stats, coalesced store ----
    float* Cs = (float*)smem;  // [128][132]
#pragma unroll
    for (int mf = 0; mf < 4; mf++) {
#pragma unroll
        for (int nf = 0; nf < 4; nf++) {
            int r0 = wm * 64 + mf * 16 + g;
            int cc = wn * 32 + nf * 8 + 2 * tig;
            Cs[r0 * 132 + cc] = c[mf][nf][0];
            Cs[r0 * 132 + cc + 1] = c[mf][nf][1];
            Cs[(r0 + 8) * 132 + cc] = c[mf][nf][2];
            Cs[(r0 + 8) * 132 + cc + 1] = c[mf][nf][3];
        }
    }
    __syncthreads();

    float* smean = (float*)(smem + SM_MEAN);
    float* srs = (float*)(smem + SM_RS);
    const float4* bp = (const float4*)(smem + SM_BIAS);

    if (tid < 128) {
        const float4* rowp = (const float4*)(Cs + tid * 132);
        float mean = 0.f;
#pragma unroll
        for (int i = 0; i < 32; i++) {
            float4 v = rowp[i], bi = bp[i];
            mean += (v.x + bi.x) + (v.y + bi.y) + (v.z + bi.z) + (v.w + bi.w);
        }
        mean *= (1.0f / 128.0f);
        float var = 0.f;
#pragma unroll
        for (int i = 0; i < 32; i++) {
            float4 v = rowp[i], bi = bp[i];
            float d0 = v.x + bi.x - mean, d1 = v.y + bi.y - mean;
            float d2 = v.z + bi.z - mean, d3 = v.w + bi.w - mean;
            var += d0 * d0 + d1 * d1 + d2 * d2 + d3 * d3;
        }
        smean[tid] = mean;
        srs[tid] = rsqrtf(var * (1.0f / 128.0f) + 1e-5f);
    }
    __syncthreads();

    const float4* gp = (const float4*)(smem + SM_G);
    const float4* bbp = (const float4*)(smem + SM_B2);
#pragma unroll
    for (int it = 0; it < 16; it++) {
        int idx = tid + it * 256;      // float4 index over 128x32
        int rrow = idx >> 5, c4 = idx & 31;
        int node = n0 + rrow;
        if (node < N_NODES) {
            float m = smean[rrow], rs = srs[rrow];
            float4 v = ((const float4*)(Cs + rrow * 132))[c4];
            float4 bi = bp[c4], gg = gp[c4], be = bbp[c4];
            float4 w;
            w.x = fmaxf((v.x + bi.x - m) * rs * gg.x + be.x, 0.f);
            w.y = fmaxf((v.y + bi.y - m) * rs * gg.y + be.y, 0.f);
            w.z = fmaxf((v.z + bi.z - m) * rs * gg.z + be.z, 0.f);
            w.w = fmaxf((v.w + bi.w - m) * rs * gg.w + be.w, 0.f);
            if (layer == 0) {
                ((uint2*)g_x1h)[(size_t)node * 32 + c4] = pack4h(w);
            } else {
                ((float4*)(out_l2 + (size_t)node * DIM))[c4] = w;
            }
        }
    }
}

// ---------------- launch ----------------
extern "C" void kernel_launch(void* const* d_in, const int* in_sizes, int n_in,
                              void* d_out, int out_size) {
    const int* ei = (const int*)d_in[0];
    const int* row = ei;
    const int* col = ei + E_EDGES;
    const int* et = (const int*)d_in[1];
    const float* emb = (const float*)d_in[2];
    const float* bases1 = (const float*)d_in[3];
    const float* coef1 = (const float*)d_in[4];
    const float* selfw1 = (const float*)d_in[5];
    const float* bias1 = (const float*)d_in[6];
    const float* g1 = (const float*)d_in[7];
    const float* b1 = (const float*)d_in[8];
    const float* bases2 = (const float*)d_in[9];
    const float* coef2 = (const float*)d_in[10];
    const float* selfw2 = (const float*)d_in[11];
    const float* bias2 = (const float*)d_in[12];
    const float* g2 = (const float*)d_in[13];
    const float* b2 = (const float*)d_in[14];
    float* out = (float*)d_out;

    static bool attr_set = false;
    if (!attr_set) {
        cudaFuncSetAttribute(k_gemm, cudaFuncAttributeMaxDynamicSharedMemorySize, SM_TOTAL);
        attr_set = true;
    }

    // edge sort by (row, relation) — shared by both layers
    k_zero<<<(NKEYS + 255) / 256, 256>>>();
    k_hist<<<(E_EDGES + 255) / 256, 256>>>(row, et);
    k_scan1<<<NBLK, 1024>>>();
    k_scan2<<<1, 1024>>>();
    k_scan3<<<NBLK, 1024>>>();
    k_scatter<<<(E_EDGES + 255) / 256, 256>>>(row, col, et);

    // emb -> fp16 for gathers
    k_cvt<<<(N_NODES * 32 + 255) / 256, 256>>>(emb);

    // weight prep (tiled transpose, fp16)
    dim3 wgrid(KDIM / 32, DIM / 32);
    dim3 wblk(32, 8);
    k_wprep<<<wgrid, wblk>>>(bases1, selfw1, 0);
    k_wprep<<<wgrid, wblk>>>(bases2, selfw2, 1);

    // layer 1
    k_agg<<<(N_NODES * 32 + 255) / 256, 256>>>(coef1, 0);
    k_gemm<<<NTILES, 256, SM_TOTAL>>>(bias1, g1, b1, 0, out);
    // layer 2
    k_agg<<<(N_NODES * 32 + 255) / 256, 256>>>(coef2, 1);
    k_gemm<<<NTILES, 256, SM_TOTAL>>>(bias2, g2, b2, 1, out);
}

// round 16
// speedup vs baseline: 1.7197x; 1.0153x over previous
#include <cuda_runtime.h>
#include <cuda_fp16.h>
#include <cstdint>

// ---------------- problem constants ----------------
#define N_NODES 50000
#define N_PAD   50048            // 391 * 128
#define R_REL   16
#define B_BASES 8
#define DIM     128
#define E_EDGES 625000
#define NKEYS   (N_NODES * R_REL)
#define NBLK    ((NKEYS + 1023) / 1024)   // 782
#define KDIM    1152             // (B+1)*D : 8 bases + selfw
#define KC      32               // K elements per pipeline stage
#define KCH     (KDIM / KC)      // 36
#define NTILES  (N_PAD / 128)    // 391

// smem tile geometry: 128 rows x KC fp16, padded to 40 elems (80 B) per row
#define TPAD    40
#define ROWB    (TPAD * 2)                // 80 bytes per row
#define TILE_B  (128 * ROWB)              // 10240 bytes
#define SA      0
#define SW      TILE_B                    // 10240
#define STAGE_B (2 * TILE_B)              // A, W = 20480
#define NSTAGE  3                         // stages end at 61440
#define SM_MEAN  67584                    // after Cs (128*132*4 = 67584), overlays stages
#define SM_RS    (SM_MEAN + 512)
#define SM_BIAS  68608
#define SM_G     (SM_BIAS + 512)
#define SM_B2    (SM_G + 512)
#define SM_TOTAL (SM_B2 + 512)            // 70144

// ---------------- scratch (device globals) ----------------
__device__ int g_hist[NKEYS];
__device__ int g_start[NKEYS + 1];
__device__ int g_cursor[NKEYS];
__device__ int g_bsums[1024];
__device__ int g_scol[E_EDGES];
__device__ __half g_Af[(size_t)N_PAD * KDIM];   // [N_pad, 1152] fp16
__device__ float g_x1[(size_t)N_PAD * DIM];     // layer-1 output
__device__ __half g_Wf[2][DIM * KDIM];          // Wt[n][k] fp16, per layer

// ---------------- helpers ----------------
__device__ __forceinline__ uint32_t smem_u32(const void* p) {
    uint32_t a;
    asm("{ .reg .u64 t; cvta.to.shared.u64 t, %1; cvt.u32.u64 %0, t; }" : "=r"(a) : "l"(p));
    return a;
}
__device__ __forceinline__ void cpa16(uint32_t dst, const void* src) {
    asm volatile("cp.async.cg.shared.global [%0], [%1], 16;" :: "r"(dst), "l"(src) : "memory");
}
__device__ __forceinline__ uint32_t lds32(uint32_t a) {
    uint32_t v;
    asm volatile("ld.shared.b32 %0, [%1];" : "=r"(v) : "r"(a));
    return v;
}
__device__ __forceinline__ void mma16816(float* c, uint32_t a0, uint32_t a1, uint32_t a2,
                                         uint32_t a3, uint32_t b0, uint32_t b1) {
    asm volatile(
        "mma.sync.aligned.m16n8k16.row.col.f32.f16.f16.f32 "
        "{%0,%1,%2,%3}, {%4,%5,%6,%7}, {%8,%9}, {%0,%1,%2,%3};"
        : "+f"(c[0]), "+f"(c[1]), "+f"(c[2]), "+f"(c[3])
        : "r"(a0), "r"(a1), "r"(a2), "r"(a3), "r"(b0), "r"(b1));
}
__device__ __forceinline__ uint2 pack4h(float4 f) {
    __half2 h0 = __floats2half2_rn(f.x, f.y);
    __half2 h1 = __floats2half2_rn(f.z, f.w);
    uint2 r;
    r.x = *reinterpret_cast<uint32_t*>(&h0);
    r.y = *reinterpret_cast<uint32_t*>(&h1);
    return r;
}

// ---------------- sort / bookkeeping kernels ----------------
__global__ void k_zero() {
    int i = blockIdx.x * blockDim.x + threadIdx.x;
    if (i < NKEYS) g_hist[i] = 0;
}
__global__ void k_hist(const int* __restrict__ row, const int* __restrict__ et) {
    int e = blockIdx.x * blockDim.x + threadIdx.x;
    if (e < E_EDGES) atomicAdd(&g_hist[row[e] * R_REL + et[e]], 1);
}
__global__ void k_scan1() {
    __shared__ int sh[1024];
    int tid = threadIdx.x;
    int i = blockIdx.x * 1024 + tid;
    int v = (i < NKEYS) ? g_hist[i] : 0;
    sh[tid] = v;
    __syncthreads();
    for (int off = 1; off < 1024; off <<= 1) {
        int t = (tid >= off) ? sh[tid - off] : 0;
        __syncthreads();
        sh[tid] += t;
        __syncthreads();
    }
    if (i < NKEYS) g_start[i] = sh[tid] - v;
    if (tid == 1023) g_bsums[blockIdx.x] = sh[1023];
}
__global__ void k_scan2() {
    __shared__ int sh[1024];
    int tid = threadIdx.x;
    int v = (tid < NBLK) ? g_bsums[tid] : 0;
    sh[tid] = v;
    __syncthreads();
    for (int off = 1; off < 1024; off <<= 1) {
        int t = (tid >= off) ? sh[tid - off] : 0;
        __syncthreads();
        sh[tid] += t;
        __syncthreads();
    }
    if (tid < NBLK) g_bsums[tid] = sh[tid] - v;
}
__global__ void k_scan3() {
    int i = blockIdx.x * 1024 + threadIdx.x;
    if (i < NKEYS) {
        int s = g_start[i] + g_bsums[blockIdx.x];
        g_start[i] = s;
        g_cursor[i] = s;
    }
    if (i == 0) g_start[NKEYS] = E_EDGES;
}
__global__ void k_scatter(const int* __restrict__ row, const int* __restrict__ col,
                          const int* __restrict__ et) {
    int e = blockIdx.x * blockDim.x + threadIdx.x;
    if (e < E_EDGES) {
        int key = row[e] * R_REL + et[e];
        int p = atomicAdd(&g_cursor[key], 1);
        g_scol[p] = col[e];
    }
}

// ---------------- weight prep: tiled transpose [1152,128] -> Wt[n][k] fp16 ----------------
__global__ void k_wprep(const float* __restrict__ bases, const float* __restrict__ selfw, int layer) {
    __shared__ float t[32][33];
    int k0 = blockIdx.x * 32, o0 = blockIdx.y * 32;
    int tx = threadIdx.x, ty = threadIdx.y;  // 32 x 8
#pragma unroll
    for (int j = 0; j < 4; j++) {
        int k = k0 + ty + j * 8;
        int o = o0 + tx;
        float v = (k < 1024) ? bases[(size_t)k * DIM + o] : selfw[(size_t)(k - 1024) * DIM + o];
        t[ty + j * 8][tx] = v;
    }
    __syncthreads();
#pragma unroll
    for (int j = 0; j < 4; j++) {
        int o = o0 + ty + j * 8;
        int k = k0 + tx;
        g_Wf[layer][(size_t)o * KDIM + k] = __float2half(t[tx][ty + j * 8]);
    }
}

// ---------------- aggregation: one warp per node, 4-way unrolled gathers ----------------
__global__ void k_agg(const float* __restrict__ x0, const float* __restrict__ coef, int layer) {
    __shared__ float sc[R_REL * B_BASES];
    int tid = threadIdx.x;
    if (tid < R_REL * B_BASES) sc[tid] = coef[tid];
    __syncthreads();

    const float* x = layer ? g_x1 : x0;
    int n = (blockIdx.x * blockDim.x + tid) >> 5;
    int lane = tid & 31;
    if (n >= N_NODES) return;

    float4 u[B_BASES];
#pragma unroll
    for (int b = 0; b < B_BASES; b++) u[b] = make_float4(0.f, 0.f, 0.f, 0.f);

    const float4* x4 = (const float4*)x;
    int base = n * R_REL;
    for (int r = 0; r < R_REL; r++) {
        int s = g_start[base + r];
        int e1 = g_start[base + r + 1];
        if (e1 > s) {
            float4 a0 = make_float4(0.f, 0.f, 0.f, 0.f);
            float4 a1 = make_float4(0.f, 0.f, 0.f, 0.f);
            int e = s;
            // 4-wide: 4 index loads + 4 gathers in flight per iteration
            for (; e + 4 <= e1; e += 4) {
                int c0 = g_scol[e], c1 = g_scol[e + 1];
                int c2 = g_scol[e + 2], c3 = g_scol[e + 3];
                float4 v0 = x4[(size_t)c0 * 32 + lane];
                float4 v1 = x4[(size_t)c1 * 32 + lane];
                float4 v2 = x4[(size_t)c2 * 32 + lane];
                float4 v3 = x4[(size_t)c3 * 32 + lane];
                a0.x += v0.x + v2.x; a0.y += v0.y + v2.y;
                a0.z += v0.z + v2.z; a0.w += v0.w + v2.w;
                a1.x += v1.x + v3.x; a1.y += v1.y + v3.y;
                a1.z += v1.z + v3.z; a1.w += v1.w + v3.w;
            }
            for (; e < e1; e++) {
                int c = g_scol[e];
                float4 v = x4[(size_t)c * 32 + lane];
                a0.x += v.x; a0.y += v.y; a0.z += v.z; a0.w += v.w;
            }
            float4 acc;
            acc.x = a0.x + a1.x; acc.y = a0.y + a1.y;
            acc.z = a0.z + a1.z; acc.w = a0.w + a1.w;
            float inv = 1.0f / (float)(e1 - s);
#pragma unroll
            for (int b = 0; b < B_BASES; b++) {
                float cb = sc[r * B_BASES + b] * inv;
                u[b].x += cb * acc.x; u[b].y += cb * acc.y;
                u[b].z += cb * acc.z; u[b].w += cb * acc.w;
            }
        }
    }

    size_t arow = (size_t)n * KDIM;
#pragma unroll
    for (int b = 0; b < B_BASES; b++)
        *(uint2*)(g_Af + arow + b * 128 + lane * 4) = pack4h(u[b]);
    *(uint2*)(g_Af + arow + 1024 + lane * 4) = pack4h(x4[(size_t)n * 32 + lane]);
}

// ---------------- fused GEMM (fp16, 3-stage cp.async, scalar LDS) + bias + LN + ReLU -------
__global__ void __launch_bounds__(256, 2) k_gemm(const float* __restrict__ bias,
                                                 const float* __restrict__ lng,
                                                 const float* __restrict__ lnb,
                                                 int layer, float* __restrict__ out_l2) {
    extern __shared__ char smem[];
    uint32_t sb = smem_u32(smem);
    int tid = threadIdx.x;
    int wid = tid >> 5, lane = tid & 31;
    int g = lane >> 2, tig = lane & 3;
    int wm = wid & 1, wn = wid >> 1;   // 2 x 4 warp grid over 128x128
    int n0 = blockIdx.x * 128;

    if (tid < 128) {
        ((float*)(smem + SM_BIAS))[tid] = bias[tid];
        ((float*)(smem + SM_G))[tid] = lng[tid];
        ((float*)(smem + SM_B2))[tid] = lnb[tid];
    }

    const __half* Wf = g_Wf[layer];
    float* out = layer ? out_l2 : g_x1;

    float c[4][4][4];
#pragma unroll
    for (int i = 0; i < 4; i++)
#pragma unroll
        for (int j = 0; j < 4; j++)
#pragma unroll
            for (int q = 0; q < 4; q++) c[i][j][q] = 0.f;

    // cp.async stage issue: 2 tiles x 128 rows x 64B; per thread 4 chunks of 16B
    int crow = tid >> 2;               // 0..63
    int cn = tid & 3;
    int coff = cn * 8;                 // fp16 element offset of 16B chunk
    size_t abase = (size_t)n0 * KDIM;

    auto issue = [&](int kc) {
        uint32_t d = sb + (kc % NSTAGE) * STAGE_B + crow * ROWB + cn * 16;
        size_t go = (size_t)crow * KDIM + kc * KC + coff;
        cpa16(d + SA, g_Af + abase + go);
        cpa16(d + SA + 64 * ROWB, g_Af + abase + go + (size_t)64 * KDIM);
        cpa16(d + SW, Wf + go);
        cpa16(d + SW + 64 * ROWB, Wf + go + (size_t)64 * KDIM);
        asm volatile("cp.async.commit_group;" ::: "memory");
    };

    issue(0);
    issue(1);

    for (int kc = 0; kc < KCH; kc++) {
        if (kc + 1 < KCH) {
            asm volatile("cp.async.wait_group 1;" ::: "memory");
        } else {
            asm volatile("cp.async.wait_group 0;" ::: "memory");
        }
        __syncthreads();
        if (kc + 2 < KCH) issue(kc + 2);

        uint32_t tA = sb + (kc % NSTAGE) * STAGE_B + SA;
        uint32_t tW = sb + (kc % NSTAGE) * STAGE_B + SW;

#pragma unroll
        for (int ks = 0; ks < 2; ks++) {
            int kb = ks * 16;
            uint32_t bh[4][2];
#pragma unroll
            for (int nf = 0; nf < 4; nf++) {
                int n = wn * 32 + nf * 8 + g;
                uint32_t o0 = n * ROWB + (kb + 2 * tig) * 2;
                bh[nf][0] = lds32(tW + o0);
                bh[nf][1] = lds32(tW + o0 + 16);
            }
#pragma unroll
            for (int mf = 0; mf < 4; mf++) {
                int r0 = wm * 64 + mf * 16 + g;
                uint32_t p = r0 * ROWB + (kb + 2 * tig) * 2;
                uint32_t a0 = lds32(tA + p);
                uint32_t a1 = lds32(tA + p + 8 * ROWB);
                uint32_t a2 = lds32(tA + p + 16);
                uint32_t a3 = lds32(tA + p + 8 * ROWB + 16);
#pragma unroll
                for (int nf = 0; nf < 4; nf++)
                    mma16816(c[mf][nf], a0, a1, a2, a3, bh[nf][0], bh[nf][1]);
            }
        }
    }
    __syncthreads();

    // ---- epilogue: C -> smem, LN stats, coalesced store ----
    float* Cs = (float*)smem;  // [128][132]
#pragma unroll
    for (int mf = 0; mf < 4; mf++) {
#pragma unroll
        for (int nf = 0; nf < 4; nf++) {
            int r0 = wm * 64 + mf * 16 + g;
            int cc = wn * 32 + nf * 8 + 2 * tig;
            Cs[r0 * 132 + cc] = c[mf][nf][0];
            Cs[r0 * 132 + cc + 1] = c[mf][nf][1];
            Cs[(r0 + 8) * 132 + cc] = c[mf][nf][2];
            Cs[(r0 + 8) * 132 + cc + 1] = c[mf][nf][3];
        }
    }
    __syncthreads();

    float* smean = (float*)(smem + SM_MEAN);
    float* srs = (float*)(smem + SM_RS);
    const float4* bp = (const float4*)(smem + SM_BIAS);

    if (tid < 128) {
        const float4* rowp = (const float4*)(Cs + tid * 132);
        float mean = 0.f;
#pragma unroll
        for (int i = 0; i < 32; i++) {
            float4 v = rowp[i], bi = bp[i];
            mean += (v.x + bi.x) + (v.y + bi.y) + (v.z + bi.z) + (v.w + bi.w);
        }
        mean *= (1.0f / 128.0f);
        float var = 0.f;
#pragma unroll
        for (int i = 0; i < 32; i++) {
            float4 v = rowp[i], bi = bp[i];
            float d0 = v.x + bi.x - mean, d1 = v.y + bi.y - mean;
            float d2 = v.z + bi.z - mean, d3 = v.w + bi.w - mean;
            var += d0 * d0 + d1 * d1 + d2 * d2 + d3 * d3;
        }
        smean[tid] = mean;
        srs[tid] = rsqrtf(var * (1.0f / 128.0f) + 1e-5f);
    }
    __syncthreads();

    const float4* gp = (const float4*)(smem + SM_G);
    const float4* bbp = (const float4*)(smem + SM_B2);
#pragma unroll
    for (int it = 0; it < 16; it++) {
        int idx = tid + it * 256;      // float4 index over 128x32
        int rrow = idx >> 5, c4 = idx & 31;
        int node = n0 + rrow;
        if (node < N_NODES) {
            float m = smean[rrow], rs = srs[rrow];
            float4 v = ((const float4*)(Cs + rrow * 132))[c4];
            float4 bi = bp[c4], gg = gp[c4], be = bbp[c4];
            float4 w;
            w.x = fmaxf((v.x + bi.x - m) * rs * gg.x + be.x, 0.f);
            w.y = fmaxf((v.y + bi.y - m) * rs * gg.y + be.y, 0.f);
            w.z = fmaxf((v.z + bi.z - m) * rs * gg.z + be.z, 0.f);
            w.w = fmaxf((v.w + bi.w - m) * rs * gg.w + be.w, 0.f);
            ((float4*)(out + (size_t)node * DIM))[c4] = w;
        }
    }
}

// ---------------- launch ----------------
extern "C" void kernel_launch(void* const* d_in, const int* in_sizes, int n_in,
                              void* d_out, int out_size) {
    const int* ei = (const int*)d_in[0];
    const int* row = ei;
    const int* col = ei + E_EDGES;
    const int* et = (const int*)d_in[1];
    const float* emb = (const float*)d_in[2];
    const float* bases1 = (const float*)d_in[3];
    const float* coef1 = (const float*)d_in[4];
    const float* selfw1 = (const float*)d_in[5];
    const float* bias1 = (const float*)d_in[6];
    const float* g1 = (const float*)d_in[7];
    const float* b1 = (const float*)d_in[8];
    const float* bases2 = (const float*)d_in[9];
    const float* coef2 = (const float*)d_in[10];
    const float* selfw2 = (const float*)d_in[11];
    const float* bias2 = (const float*)d_in[12];
    const float* g2 = (const float*)d_in[13];
    const float* b2 = (const float*)d_in[14];
    float* out = (float*)d_out;

    static bool attr_set = false;
    if (!attr_set) {
        cudaFuncSetAttribute(k_gemm, cudaFuncAttributeMaxDynamicSharedMemorySize, SM_TOTAL);
        attr_set = true;
    }

    // edge sort by (row, relation) — shared by both layers
    k_zero<<<(NKEYS + 255) / 256, 256>>>();
    k_hist<<<(E_EDGES + 255) / 256, 256>>>(row, et);
    k_scan1<<<NBLK, 1024>>>();
    k_scan2<<<1, 1024>>>();
    k_scan3<<<NBLK, 1024>>>();
    k_scatter<<<(E_EDGES + 255) / 256, 256>>>(row, col, et);

    // weight prep (tiled transpose, fp16)
    dim3 wgrid(KDIM / 32, DIM / 32);
    dim3 wblk(32, 8);
    k_wprep<<<wgrid, wblk>>>(bases1, selfw1, 0);
    k_wprep<<<wgrid, wblk>>>(bases2, selfw2, 1);

    // layer 1
    k_agg<<<(N_NODES * 32 + 255) / 256, 256>>>(emb, coef1, 0);
    k_gemm<<<NTILES, 256, SM_TOTAL>>>(bias1, g1, b1, 0, out);
    // layer 2
    k_agg<<<(N_NODES * 32 + 255) / 256, 256>>>(emb, coef2, 1);
    k_gemm<<<NTILES, 256, SM_TOTAL>>>(bias2, g2, b2, 1, out);
}

// round 17
// speedup vs baseline: 1.7516x; 1.0186x over previous
#include <cuda_runtime.h>
#include <cuda_fp16.h>
#include <cstdint>

// ---------------- problem constants ----------------
#define N_NODES 50000
#define N_PAD   50048            // 391 * 128
#define R_REL   16
#define B_BASES 8
#define DIM     128
#define E_EDGES 625000
#define NKEYS   (N_NODES * R_REL)
#define NBLK    ((NKEYS + 1023) / 1024)   // 782
#define KDIM    1152             // (B+1)*D : 8 bases + selfw
#define KC      32               // K elements per pipeline stage
#define KCH     (KDIM / KC)      // 36
#define NTILES  (N_PAD / 128)    // 391
#define GGRID   296              // persistent GEMM grid: 2 CTAs x 148 SMs

// smem tile geometry: 128 rows x KC fp16, padded to 40 elems (80 B) per row
#define TPAD    40
#define ROWB    (TPAD * 2)                // 80 bytes per row
#define TILE_B  (128 * ROWB)              // 10240 bytes
#define SA      0
#define SW      TILE_B                    // 10240
#define STAGE_B (2 * TILE_B)              // A, W = 20480
#define NSTAGE  3                         // stages end at 61440
#define SM_MEAN  67584                    // after Cs (128*132*4 = 67584), overlays stages
#define SM_RS    (SM_MEAN + 512)
#define SM_BIAS  68608
#define SM_G     (SM_BIAS + 512)
#define SM_B2    (SM_G + 512)
#define SM_TOTAL (SM_B2 + 512)            // 70144

// ---------------- scratch (device globals) ----------------
__device__ int g_hist[NKEYS];
__device__ int g_start[NKEYS + 1];
__device__ int g_cursor[NKEYS];
__device__ int g_bsums[1024];
__device__ int g_tile[2];                       // per-layer tile tickets (reset by k_zero)
__device__ int g_scol[E_EDGES];
__device__ __half g_Af[(size_t)N_PAD * KDIM];   // [N_pad, 1152] fp16
__device__ float g_x1[(size_t)N_PAD * DIM];     // layer-1 output
__device__ __half g_Wf[2][DIM * KDIM];          // Wt[n][k] fp16, per layer

// ---------------- helpers ----------------
__device__ __forceinline__ uint32_t smem_u32(const void* p) {
    uint32_t a;
    asm("{ .reg .u64 t; cvta.to.shared.u64 t, %1; cvt.u32.u64 %0, t; }" : "=r"(a) : "l"(p));
    return a;
}
__device__ __forceinline__ void cpa16(uint32_t dst, const void* src) {
    asm volatile("cp.async.cg.shared.global [%0], [%1], 16;" :: "r"(dst), "l"(src) : "memory");
}
__device__ __forceinline__ uint32_t lds32(uint32_t a) {
    uint32_t v;
    asm volatile("ld.shared.b32 %0, [%1];" : "=r"(v) : "r"(a));
    return v;
}
__device__ __forceinline__ void mma16816(float* c, uint32_t a0, uint32_t a1, uint32_t a2,
                                         uint32_t a3, uint32_t b0, uint32_t b1) {
    asm volatile(
        "mma.sync.aligned.m16n8k16.row.col.f32.f16.f16.f32 "
        "{%0,%1,%2,%3}, {%4,%5,%6,%7}, {%8,%9}, {%0,%1,%2,%3};"
        : "+f"(c[0]), "+f"(c[1]), "+f"(c[2]), "+f"(c[3])
        : "r"(a0), "r"(a1), "r"(a2), "r"(a3), "r"(b0), "r"(b1));
}
__device__ __forceinline__ uint2 pack4h(float4 f) {
    __half2 h0 = __floats2half2_rn(f.x, f.y);
    __half2 h1 = __floats2half2_rn(f.z, f.w);
    uint2 r;
    r.x = *reinterpret_cast<uint32_t*>(&h0);
    r.y = *reinterpret_cast<uint32_t*>(&h1);
    return r;
}

// ---------------- sort / bookkeeping kernels ----------------
__global__ void k_zero() {
    int i = blockIdx.x * blockDim.x + threadIdx.x;
    if (i < NKEYS) g_hist[i] = 0;
    if (i < 2) g_tile[i] = 0;
}
__global__ void k_hist(const int* __restrict__ row, const int* __restrict__ et) {
    int e = blockIdx.x * blockDim.x + threadIdx.x;
    if (e < E_EDGES) atomicAdd(&g_hist[row[e] * R_REL + et[e]], 1);
}
__global__ void k_scan1() {
    __shared__ int sh[1024];
    int tid = threadIdx.x;
    int i = blockIdx.x * 1024 + tid;
    int v = (i < NKEYS) ? g_hist[i] : 0;
    sh[tid] = v;
    __syncthreads();
    for (int off = 1; off < 1024; off <<= 1) {
        int t = (tid >= off) ? sh[tid - off] : 0;
        __syncthreads();
        sh[tid] += t;
        __syncthreads();
    }
    if (i < NKEYS) g_start[i] = sh[tid] - v;
    if (tid == 1023) g_bsums[blockIdx.x] = sh[1023];
}
__global__ void k_scan2() {
    __shared__ int sh[1024];
    int tid = threadIdx.x;
    int v = (tid < NBLK) ? g_bsums[tid] : 0;
    sh[tid] = v;
    __syncthreads();
    for (int off = 1; off < 1024; off <<= 1) {
        int t = (tid >= off) ? sh[tid - off] : 0;
        __syncthreads();
        sh[tid] += t;
        __syncthreads();
    }
    if (tid < NBLK) g_bsums[tid] = sh[tid] - v;
}
__global__ void k_scan3() {
    int i = blockIdx.x * 1024 + threadIdx.x;
    if (i < NKEYS) {
        int s = g_start[i] + g_bsums[blockIdx.x];
        g_start[i] = s;
        g_cursor[i] = s;
    }
    if (i == 0) g_start[NKEYS] = E_EDGES;
}
__global__ void k_scatter(const int* __restrict__ row, const int* __restrict__ col,
                          const int* __restrict__ et) {
    int e = blockIdx.x * blockDim.x + threadIdx.x;
    if (e < E_EDGES) {
        int key = row[e] * R_REL + et[e];
        int p = atomicAdd(&g_cursor[key], 1);
        g_scol[p] = col[e];
    }
}

// ---------------- weight prep: tiled transpose [1152,128] -> Wt[n][k] fp16 ----------------
__global__ void k_wprep(const float* __restrict__ bases, const float* __restrict__ selfw, int layer) {
    __shared__ float t[32][33];
    int k0 = blockIdx.x * 32, o0 = blockIdx.y * 32;
    int tx = threadIdx.x, ty = threadIdx.y;  // 32 x 8
#pragma unroll
    for (int j = 0; j < 4; j++) {
        int k = k0 + ty + j * 8;
        int o = o0 + tx;
        float v = (k < 1024) ? bases[(size_t)k * DIM + o] : selfw[(size_t)(k - 1024) * DIM + o];
        t[ty + j * 8][tx] = v;
    }
    __syncthreads();
#pragma unroll
    for (int j = 0; j < 4; j++) {
        int o = o0 + ty + j * 8;
        int k = k0 + tx;
        g_Wf[layer][(size_t)o * KDIM + k] = __float2half(t[tx][ty + j * 8]);
    }
}

// ---------------- aggregation: one warp per node, 4-way unrolled gathers ----------------
__global__ void k_agg(const float* __restrict__ x0, const float* __restrict__ coef, int layer) {
    __shared__ float sc[R_REL * B_BASES];
    int tid = threadIdx.x;
    if (tid < R_REL * B_BASES) sc[tid] = coef[tid];
    __syncthreads();

    const float* x = layer ? g_x1 : x0;
    int n = (blockIdx.x * blockDim.x + tid) >> 5;
    int lane = tid & 31;
    if (n >= N_NODES) return;

    float4 u[B_BASES];
#pragma unroll
    for (int b = 0; b < B_BASES; b++) u[b] = make_float4(0.f, 0.f, 0.f, 0.f);

    const float4* x4 = (const float4*)x;
    int base = n * R_REL;
    for (int r = 0; r < R_REL; r++) {
        int s = g_start[base + r];
        int e1 = g_start[base + r + 1];
        if (e1 > s) {
            float4 a0 = make_float4(0.f, 0.f, 0.f, 0.f);
            float4 a1 = make_float4(0.f, 0.f, 0.f, 0.f);
            int e = s;
            for (; e + 4 <= e1; e += 4) {
                int c0 = g_scol[e], c1 = g_scol[e + 1];
                int c2 = g_scol[e + 2], c3 = g_scol[e + 3];
                float4 v0 = x4[(size_t)c0 * 32 + lane];
                float4 v1 = x4[(size_t)c1 * 32 + lane];
                float4 v2 = x4[(size_t)c2 * 32 + lane];
                float4 v3 = x4[(size_t)c3 * 32 + lane];
                a0.x += v0.x + v2.x; a0.y += v0.y + v2.y;
                a0.z += v0.z + v2.z; a0.w += v0.w + v2.w;
                a1.x += v1.x + v3.x; a1.y += v1.y + v3.y;
                a1.z += v1.z + v3.z; a1.w += v1.w + v3.w;
            }
            for (; e < e1; e++) {
                int c = g_scol[e];
                float4 v = x4[(size_t)c * 32 + lane];
                a0.x += v.x; a0.y += v.y; a0.z += v.z; a0.w += v.w;
            }
            float4 acc;
            acc.x = a0.x + a1.x; acc.y = a0.y + a1.y;
            acc.z = a0.z + a1.z; acc.w = a0.w + a1.w;
            float inv = 1.0f / (float)(e1 - s);
#pragma unroll
            for (int b = 0; b < B_BASES; b++) {
                float cb = sc[r * B_BASES + b] * inv;
                u[b].x += cb * acc.x; u[b].y += cb * acc.y;
                u[b].z += cb * acc.z; u[b].w += cb * acc.w;
            }
        }
    }

    size_t arow = (size_t)n * KDIM;
#pragma unroll
    for (int b = 0; b < B_BASES; b++)
        *(uint2*)(g_Af + arow + b * 128 + lane * 4) = pack4h(u[b]);
    *(uint2*)(g_Af + arow + 1024 + lane * 4) = pack4h(x4[(size_t)n * 32 + lane]);
}

// ---------------- persistent fused GEMM (dynamic tile ticket) + bias + LN + ReLU ----------
__global__ void __launch_bounds__(256, 2) k_gemm(const float* __restrict__ bias,
                                                 const float* __restrict__ lng,
                                                 const float* __restrict__ lnb,
                                                 int layer, float* __restrict__ out_l2) {
    extern __shared__ char smem[];
    uint32_t sb = smem_u32(smem);
    int tid = threadIdx.x;
    int wid = tid >> 5, lane = tid & 31;
    int g = lane >> 2, tig = lane & 3;
    int wm = wid & 1, wn = wid >> 1;   // 2 x 4 warp grid over 128x128

    if (tid < 128) {
        ((float*)(smem + SM_BIAS))[tid] = bias[tid];
        ((float*)(smem + SM_G))[tid] = lng[tid];
        ((float*)(smem + SM_B2))[tid] = lnb[tid];
    }

    const __half* Wf = g_Wf[layer];
    float* out = layer ? out_l2 : g_x1;

    int crow = tid >> 2;               // 0..63
    int cn = tid & 3;
    int coff = cn * 8;                 // fp16 element offset of 16B chunk

    __shared__ int stile;

    while (true) {
        if (tid == 0) stile = atomicAdd(&g_tile[layer], 1);
        __syncthreads();               // also fences previous tile's epilogue vs new loads
        int tile = stile;
        if (tile >= NTILES) break;
        int n0 = tile * 128;
        size_t abase = (size_t)n0 * KDIM;

        float c[4][4][4];
#pragma unroll
        for (int i = 0; i < 4; i++)
#pragma unroll
            for (int j = 0; j < 4; j++)
#pragma unroll
                for (int q = 0; q < 4; q++) c[i][j][q] = 0.f;

        auto issue = [&](int kc) {
            uint32_t d = sb + (kc % NSTAGE) * STAGE_B + crow * ROWB + cn * 16;
            size_t go = (size_t)crow * KDIM + kc * KC + coff;
            cpa16(d + SA, g_Af + abase + go);
            cpa16(d + SA + 64 * ROWB, g_Af + abase + go + (size_t)64 * KDIM);
            cpa16(d + SW, Wf + go);
            cpa16(d + SW + 64 * ROWB, Wf + go + (size_t)64 * KDIM);
            asm volatile("cp.async.commit_group;" ::: "memory");
        };

        issue(0);
        issue(1);

        for (int kc = 0; kc < KCH; kc++) {
            if (kc + 1 < KCH) {
                asm volatile("cp.async.wait_group 1;" ::: "memory");
            } else {
                asm volatile("cp.async.wait_group 0;" ::: "memory");
            }
            __syncthreads();
            if (kc + 2 < KCH) issue(kc + 2);

            uint32_t tA = sb + (kc % NSTAGE) * STAGE_B + SA;
            uint32_t tW = sb + (kc % NSTAGE) * STAGE_B + SW;

#pragma unroll
            for (int ks = 0; ks < 2; ks++) {
                int kb = ks * 16;
                uint32_t bh[4][2];
#pragma unroll
                for (int nf = 0; nf < 4; nf++) {
                    int n = wn * 32 + nf * 8 + g;
                    uint32_t o0 = n * ROWB + (kb + 2 * tig) * 2;
                    bh[nf][0] = lds32(tW + o0);
                    bh[nf][1] = lds32(tW + o0 + 16);
                }
#pragma unroll
                for (int mf = 0; mf < 4; mf++) {
                    int r0 = wm * 64 + mf * 16 + g;
                    uint32_t p = r0 * ROWB + (kb + 2 * tig) * 2;
                    uint32_t a0 = lds32(tA + p);
                    uint32_t a1 = lds32(tA + p + 8 * ROWB);
                    uint32_t a2 = lds32(tA + p + 16);
                    uint32_t a3 = lds32(tA + p + 8 * ROWB + 16);
#pragma unroll
                    for (int nf = 0; nf < 4; nf++)
                        mma16816(c[mf][nf], a0, a1, a2, a3, bh[nf][0], bh[nf][1]);
                }
            }
        }
        __syncthreads();

        // ---- epilogue: C -> smem, LN stats, coalesced store ----
        float* Cs = (float*)smem;  // [128][132]
#pragma unroll
        for (int mf = 0; mf < 4; mf++) {
#pragma unroll
            for (int nf = 0; nf < 4; nf++) {
                int r0 = wm * 64 + mf * 16 + g;
                int cc = wn * 32 + nf * 8 + 2 * tig;
                Cs[r0 * 132 + cc] = c[mf][nf][0];
                Cs[r0 * 132 + cc + 1] = c[mf][nf][1];
                Cs[(r0 + 8) * 132 + cc] = c[mf][nf][2];
                Cs[(r0 + 8) * 132 + cc + 1] = c[mf][nf][3];
            }
        }
        __syncthreads();

        float* smean = (float*)(smem + SM_MEAN);
        float* srs = (float*)(smem + SM_RS);
        const float4* bp = (const float4*)(smem + SM_BIAS);

        if (tid < 128) {
            const float4* rowp = (const float4*)(Cs + tid * 132);
            float mean = 0.f;
#pragma unroll
            for (int i = 0; i < 32; i++) {
                float4 v = rowp[i], bi = bp[i];
                mean += (v.x + bi.x) + (v.y + bi.y) + (v.z + bi.z) + (v.w + bi.w);
            }
            mean *= (1.0f / 128.0f);
            float var = 0.f;
#pragma unroll
            for (int i = 0; i < 32; i++) {
                float4 v = rowp[i], bi = bp[i];
                float d0 = v.x + bi.x - mean, d1 = v.y + bi.y - mean;
                float d2 = v.z + bi.z - mean, d3 = v.w + bi.w - mean;
                var += d0 * d0 + d1 * d1 + d2 * d2 + d3 * d3;
            }
            smean[tid] = mean;
            srs[tid] = rsqrtf(var * (1.0f / 128.0f) + 1e-5f);
        }
        __syncthreads();

        const float4* gp = (const float4*)(smem + SM_G);
        const float4* bbp = (const float4*)(smem + SM_B2);
#pragma unroll
        for (int it = 0; it < 16; it++) {
            int idx = tid + it * 256;      // float4 index over 128x32
            int rrow = idx >> 5, c4 = idx & 31;
            int node = n0 + rrow;
            if (node < N_NODES) {
                float m = smean[rrow], rs = srs[rrow];
                float4 v = ((const float4*)(Cs + rrow * 132))[c4];
                float4 bi = bp[c4], gg = gp[c4], be = bbp[c4];
                float4 w;
                w.x = fmaxf((v.x + bi.x - m) * rs * gg.x + be.x, 0.f);
                w.y = fmaxf((v.y + bi.y - m) * rs * gg.y + be.y, 0.f);
                w.z = fmaxf((v.z + bi.z - m) * rs * gg.z + be.z, 0.f);
                w.w = fmaxf((v.w + bi.w - m) * rs * gg.w + be.w, 0.f);
                ((float4*)(out + (size_t)node * DIM))[c4] = w;
            }
        }
        // loop: top-of-loop __syncthreads orders this epilogue before next tile's loads
    }
}

// ---------------- launch ----------------
extern "C" void kernel_launch(void* const* d_in, const int* in_sizes, int n_in,
                              void* d_out, int out_size) {
    const int* ei = (const int*)d_in[0];
    const int* row = ei;
    const int* col = ei + E_EDGES;
    const int* et = (const int*)d_in[1];
    const float* emb = (const float*)d_in[2];
    const float* bases1 = (const float*)d_in[3];
    const float* coef1 = (const float*)d_in[4];
    const float* selfw1 = (const float*)d_in[5];
    const float* bias1 = (const float*)d_in[6];
    const float* g1 = (const float*)d_in[7];
    const float* b1 = (const float*)d_in[8];
    const float* bases2 = (const float*)d_in[9];
    const float* coef2 = (const float*)d_in[10];
    const float* selfw2 = (const float*)d_in[11];
    const float* bias2 = (const float*)d_in[12];
    const float* g2 = (const float*)d_in[13];
    const float* b2 = (const float*)d_in[14];
    float* out = (float*)d_out;

    static bool attr_set = false;
    if (!attr_set) {
        cudaFuncSetAttribute(k_gemm, cudaFuncAttributeMaxDynamicSharedMemorySize, SM_TOTAL);
        attr_set = true;
    }

    // edge sort by (row, relation) — shared by both layers (also resets tile tickets)
    k_zero<<<(NKEYS + 255) / 256, 256>>>();
    k_hist<<<(E_EDGES + 255) / 256, 256>>>(row, et);
    k_scan1<<<NBLK, 1024>>>();
    k_scan2<<<1, 1024>>>();
    k_scan3<<<NBLK, 1024>>>();
    k_scatter<<<(E_EDGES + 255) / 256, 256>>>(row, col, et);

    // weight prep (tiled transpose, fp16)
    dim3 wgrid(KDIM / 32, DIM / 32);
    dim3 wblk(32, 8);
    k_wprep<<<wgrid, wblk>>>(bases1, selfw1, 0);
    k_wprep<<<wgrid, wblk>>>(bases2, selfw2, 1);

    // layer 1
    k_agg<<<(N_NODES * 32 + 255) / 256, 256>>>(emb, coef1, 0);
    k_gemm<<<GGRID, 256, SM_TOTAL>>>(bias1, g1, b1, 0, out);
    // layer 2
    k_agg<<<(N_NODES * 32 + 255) / 256, 256>>>(emb, coef2, 1);
    k_gemm<<<GGRID, 256, SM_TOTAL>>>(bias2, g2, b2, 1, out);
}